// round 14
// baseline (speedup 1.0000x reference)
#include <cuda_runtime.h>
#include <cuda_fp16.h>
#include <math.h>
#include <stdint.h>

#define N_TEST  8192
#define M_TRAIN 16384
#define D_DIM   512
#define BM      128
#define BN      128
#define BK      64
#define THREADS 256
#define NBUF    5
#define NCT     ((N_TEST / BM) * (M_TRAIN / BN))   // 8192 col-tiles
#define KSTEPS  (D_DIM / BK)                       // 8
#define MAXCTAS 512

#define AST 520                              // A smem row stride (u16)
#define BST 72                               // B smem row stride (u16), 144B = 9*16

#define SMEM_A        0
#define SMEM_A_BYTES  (BM * AST * 2)         // 133120
#define SMEM_B        SMEM_A_BYTES
#define B_STAGE_BYTES (BN * BST * 2)         // 18432
#define SMEM_YS       (SMEM_B + NBUF * B_STAGE_BYTES)   // 225280
#define SMEM_RED      (SMEM_YS + 512)
#define SMEM_TOTAL    (SMEM_RED + 2048)              // 227840

// ---------------- device scratch ----------------
__device__ __half g_Xh[N_TEST * D_DIM];
__device__ __half g_Yh[M_TRAIN * D_DIM];
__device__ float g_x2s[N_TEST];      // -0.5*log2(e)*||x||^2
__device__ float g_y2s[M_TRAIN];     // -0.5*log2(e)*||y||^2
__device__ float g_pm[2 * MAXCTAS * BM];     // per (CTA, segment) partials
__device__ float g_ps[2 * MAXCTAS * BM];

// ---------------- helpers ----------------
__device__ __forceinline__ uint32_t smem_u32(const void* p) {
    uint32_t a;
    asm("{ .reg .u64 t; cvta.to.shared.u64 t, %1; cvt.u32.u64 %0, t; }" : "=r"(a) : "l"(p));
    return a;
}
__device__ __forceinline__ float ex2f(float x) {
    float y; asm("ex2.approx.ftz.f32 %0, %1;" : "=f"(y) : "f"(x)); return y;
}
__device__ __forceinline__ void cp16(uint32_t s, const void* g) {
    asm volatile("cp.async.cg.shared.global [%0], [%1], 16;" :: "r"(s), "l"(g));
}
#define CP_COMMIT() asm volatile("cp.async.commit_group;" ::: "memory")
#define CP_WAIT3()  asm volatile("cp.async.wait_group 3;" ::: "memory")

#define LDSM4(r, addr) \
    asm volatile("ldmatrix.sync.aligned.m8n8.x4.shared.b16 {%0,%1,%2,%3}, [%4];" \
        : "=r"((r)[0]), "=r"((r)[1]), "=r"((r)[2]), "=r"((r)[3]) : "r"(addr))
#define LDSM2(r, addr) \
    asm volatile("ldmatrix.sync.aligned.m8n8.x2.shared.b16 {%0,%1}, [%2];" \
        : "=r"((r)[0]), "=r"((r)[1]) : "r"(addr))

// fp16 inputs, fp16 accumulate (2 regs C/D)
#define MMA16816H(c, a, b) \
    asm volatile("mma.sync.aligned.m16n8k16.row.col.f16.f16.f16.f16 " \
        "{%0,%1},{%2,%3,%4,%5},{%6,%7},{%0,%1};" \
        : "+r"((c)[0]), "+r"((c)[1]) \
        : "r"((a)[0]), "r"((a)[1]), "r"((a)[2]), "r"((a)[3]), \
          "r"((b)[0]), "r"((b)[1]))

// ---------------------------------------------------------------------------
// Convert fp32 -> fp16 + scaled squared norms. One warp per row (R10 form).
// ---------------------------------------------------------------------------
__global__ void convert_kernel(const float* __restrict__ X,
                               const float* __restrict__ Y) {
    const float NHL2E = -0.5f * 1.4426950408889634f;
    int gw   = (blockIdx.x * blockDim.x + threadIdx.x) >> 5;
    int lane = threadIdx.x & 31;
    if (gw >= N_TEST + M_TRAIN) return;

    const float* src;
    __half* dst;
    if (gw < N_TEST) { src = X + (size_t)gw * D_DIM; dst = g_Xh + (size_t)gw * D_DIM; }
    else { src = Y + (size_t)(gw - N_TEST) * D_DIM; dst = g_Yh + (size_t)(gw - N_TEST) * D_DIM; }

    const float4* p = (const float4*)(src + lane * 16);
    __half tmp[16];
    float s = 0.f;
#pragma unroll
    for (int j = 0; j < 4; ++j) {
        float4 v = p[j];
        s += v.x * v.x + v.y * v.y + v.z * v.z + v.w * v.w;
        tmp[4 * j + 0] = __float2half_rn(v.x);
        tmp[4 * j + 1] = __float2half_rn(v.y);
        tmp[4 * j + 2] = __float2half_rn(v.z);
        tmp[4 * j + 3] = __float2half_rn(v.w);
    }
    uint4* dv = (uint4*)(dst + lane * 16);
    dv[0] = ((uint4*)tmp)[0];
    dv[1] = ((uint4*)tmp)[1];
#pragma unroll
    for (int o = 16; o; o >>= 1) s += __shfl_xor_sync(0xffffffffu, s, o);
    if (lane == 0) {
        if (gw < N_TEST) g_x2s[gw] = NHL2E * s;
        else             g_y2s[gw - N_TEST] = NHL2E * s;
    }
}

// ---------------------------------------------------------------------------
// B stage fill: local stage l covers train rows [colbase + (l/8)*BN, +BN),
// k chunk (l%8)*64 elems (128 bytes/row). 256 threads x 4 cp16 = 16 KB.
// ---------------------------------------------------------------------------
__device__ __forceinline__ void fill_stage(uint32_t sb, int colbase, int l, int tid) {
    int buf = l % NBUF;
    int t   = l >> 3;
    int ks  = l & 7;
    int row = tid >> 1;               // 0..127
    int h   = (tid & 1) * 4;          // first 16B-chunk of this thread's 64B
    const __half* gp =
        g_Yh + ((size_t)(colbase + t * BN + row)) * D_DIM + ks * BK + h * 8;
    uint32_t sa = sb + SMEM_B + buf * B_STAGE_BYTES + (uint32_t)(row * BST + h * 8) * 2;
#pragma unroll
    for (int q = 0; q < 4; ++q)
        cp16(sa + q * 16, gp + q * 8);
}

// ---------------------------------------------------------------------------
// Persistent fused kernel: each CTA owns a contiguous range of the 8192
// rt-major col-tiles (<= 2 row-tile segments). 5-buffer / depth-4 pipeline.
// ---------------------------------------------------------------------------
__global__ __launch_bounds__(THREADS, 1)
void kde_mma_kernel() {
    extern __shared__ __align__(16) unsigned char smem[];
    const uint32_t sb = smem_u32(smem);

    const int tid  = threadIdx.x;
    const int lane = tid & 31;
    const int warp = tid >> 5;
    const int wm   = warp & 3;
    const int wn   = warp >> 2;

    const int g = gridDim.x;
    int       i    = (int)(((long long)blockIdx.x * NCT) / g);
    const int iend = (int)(((long long)(blockIdx.x + 1) * NCT) / g);

    const uint32_t aRowBase = sb + SMEM_A +
        (uint32_t)((wm * 32 + (lane & 15)) * AST + (lane >> 4) * 8) * 2;
    const uint32_t bLaneOff =
        (uint32_t)((wn * 64 + (lane & 7)) * BST + ((lane >> 3) & 1) * 8) * 2;

    float* ysf  = (float*)(smem + SMEM_YS);
    float* redm = (float*)(smem + SMEM_RED);
    float* reds = (float*)(smem + SMEM_RED + 1024);
    const float L2E = 1.4426950408889634f;

    int seg = 0;
    while (i < iend) {
        const int rt     = i >> 7;
        const int segEnd = min(iend, (rt + 1) << 7);
        const int ntiles = segEnd - i;
        const int col0   = (i - (rt << 7)) * BN;
        const int row0   = rt * BM;
        const int ustages = ntiles * KSTEPS;

        // ---- A fill for this segment's row-tile ----
        {
            const __half* gp = g_Xh + (size_t)row0 * D_DIM;
#pragma unroll
            for (int q = 0; q < 32; ++q) {
                int f = tid + q * THREADS;
                int r = f >> 6, c = f & 63;
                cp16(sb + SMEM_A + (uint32_t)(r * AST + c * 8) * 2,
                     gp + (size_t)r * D_DIM + c * 8);
            }
            CP_COMMIT();
        }
        float x2p[4];
#pragma unroll
        for (int rg = 0; rg < 4; ++rg)
            x2p[rg] = g_x2s[row0 + wm * 32 + (rg >> 1) * 16 + (rg & 1) * 8 + (lane >> 2)];

        // B prologue: stages 0..3 (prefetch depth 4)
        fill_stage(sb, col0, 0, tid); CP_COMMIT();
        fill_stage(sb, col0, 1, tid); CP_COMMIT();
        fill_stage(sb, col0, 2, tid); CP_COMMIT();
        fill_stage(sb, col0, 3, tid); CP_COMMIT();

        float mrun[4], srun[4];
#pragma unroll
        for (int rg = 0; rg < 4; ++rg) { mrun[rg] = -INFINITY; srun[rg] = 0.f; }

#pragma unroll 1
        for (int t = 0; t < ntiles; ++t) {
            if (tid < BN) ysf[tid] = g_y2s[col0 + t * BN + tid];

            uint32_t acc[2][8][2];
#pragma unroll
            for (int mt = 0; mt < 2; ++mt)
#pragma unroll
                for (int nt = 0; nt < 8; ++nt) { acc[mt][nt][0] = 0u; acc[mt][nt][1] = 0u; }

#pragma unroll 1
            for (int ks = 0; ks < KSTEPS; ++ks) {
                const int l   = t * KSTEPS + ks;
                const int buf = l % NBUF;

                CP_WAIT3();            // stage l (and A on l=0) landed; 3 in flight
                __syncthreads();
                // write buf (l+4)%NBUF == (l-1)%NBUF: reads of stage l-1 are
                // behind the barrier above, so reuse is safe.
                if (l + 4 < ustages) fill_stage(sb, col0, l + 4, tid);
                CP_COMMIT();           // empty commits at the tail keep invariant

                const uint32_t bBase = sb + SMEM_B + buf * B_STAGE_BYTES + bLaneOff;
                const uint32_t aCol  = (uint32_t)(ks * BK) * 2;
#pragma unroll
                for (int kk = 0; kk < 4; ++kk) {
                    uint32_t a[2][4];
                    uint32_t aaddr = aRowBase + aCol + kk * 32;
                    LDSM4(a[0], aaddr);
                    LDSM4(a[1], aaddr + 16 * AST * 2);
                    uint32_t b[8][2];
#pragma unroll
                    for (int nt = 0; nt < 8; ++nt)
                        LDSM2(b[nt], bBase + kk * 32 + nt * 8 * BST * 2);
#pragma unroll
                    for (int mt = 0; mt < 2; ++mt)
#pragma unroll
                        for (int nt = 0; nt < 8; ++nt)
                            MMA16816H(acc[mt][nt], a[mt], b[nt]);
                }
            }

            // ---- epilogue: unpack fp16 accums, online logsumexp (f-domain) ----
            float2 yv[8];
#pragma unroll
            for (int nt = 0; nt < 8; ++nt)
                yv[nt] = *(const float2*)&ysf[wn * 64 + nt * 8 + (lane & 3) * 2];

#pragma unroll
            for (int rg = 0; rg < 4; ++rg) {
                const int mt = rg >> 1, hf = rg & 1;
                float e[16];
                float vmax = mrun[rg];
#pragma unroll
                for (int nt = 0; nt < 8; ++nt) {
                    float2 d = __half22float2(*(const __half2*)&acc[mt][nt][hf]);
                    float e0 = fmaf(d.x, L2E, yv[nt].x);
                    float e1 = fmaf(d.y, L2E, yv[nt].y);
                    e[nt * 2 + 0] = e0;
                    e[nt * 2 + 1] = e1;
                    vmax = fmaxf(vmax, fmaxf(e0, e1));
                }
                if (vmax > mrun[rg]) { srun[rg] *= ex2f(mrun[rg] - vmax); mrun[rg] = vmax; }
                float s0 = 0.f, s1 = 0.f;
#pragma unroll
                for (int j = 0; j < 16; j += 2) {
                    s0 += ex2f(e[j]     - mrun[rg]);
                    s1 += ex2f(e[j + 1] - mrun[rg]);
                }
                srun[rg] += s0 + s1;
            }
            __syncthreads();   // epilogue done before ys/buf reuse
        }

        // ---- per-segment reduction: quad shfl, then the 2 n-warps via smem ----
#pragma unroll
        for (int rg = 0; rg < 4; ++rg) {
            float m = mrun[rg] + x2p[rg];   // fold row constant back in
            float s = srun[rg];
#pragma unroll
            for (int off = 1; off <= 2; off <<= 1) {
                float mo = __shfl_xor_sync(0xffffffffu, m, off);
                float so = __shfl_xor_sync(0xffffffffu, s, off);
                float mx = fmaxf(m, mo);
                s = s * ex2f(m - mx) + so * ex2f(mo - mx);
                m = mx;
            }
            if ((lane & 3) == 0) {
                int r = wm * 32 + (rg >> 1) * 16 + (rg & 1) * 8 + (lane >> 2);
                redm[r * 2 + wn] = m;
                reds[r * 2 + wn] = s;
            }
        }
        __syncthreads();
        if (tid < BM) {
            float m0 = redm[tid * 2], m1 = redm[tid * 2 + 1];
            float s0 = reds[tid * 2], s1 = reds[tid * 2 + 1];
            float mx = fmaxf(m0, m1);
            float st = s0 * ex2f(m0 - mx) + s1 * ex2f(m1 - mx);
            int slot = blockIdx.x * 2 + seg;
            g_pm[slot * BM + tid] = mx;
            g_ps[slot * BM + tid] = st;
        }
        __syncthreads();   // red free before next segment

        seg++;
        i = segEnd;
    }
}

// ---------------------------------------------------------------------------
// Combine: for each output row, gather the (CTA, segment) slots whose
// col-tile range intersects this row-tile, and logsumexp-combine them.
// ---------------------------------------------------------------------------
__global__ void combine_kernel(float* __restrict__ out, float z, int g) {
    int r = blockIdx.x * blockDim.x + threadIdx.x;
    if (r >= N_TEST) return;
    int rt = r >> 7, rl = r & 127;

    int kmin = (int)(((long long)rt * 128 * g) / NCT) - 1;
    if (kmin < 0) kmin = 0;
    int kmax = (int)(((long long)(rt + 1) * 128 * g) / NCT) + 1;
    if (kmax > g - 1) kmax = g - 1;

    float m = -INFINITY, s = 0.f;
    for (int k = kmin; k <= kmax; ++k) {
        long long a0 = ((long long)k * NCT) / g;
        long long a1 = ((long long)(k + 1) * NCT) / g;
        int rt0 = (int)(a0 >> 7);
        int rtl = (int)((a1 - 1) >> 7);
        if (rt < rt0 || rt > rtl) continue;
        int slot = k * 2 + (rt - rt0);
        float mk = g_pm[slot * BM + rl];
        float sk = g_ps[slot * BM + rl];
        float mx = fmaxf(m, mk);
        s = s * ex2f(m - mx) + sk * ex2f(mk - mx);
        m = mx;
    }
    out[r] = m * 0.6931471805599453f + logf(s) - z;
}

// ---------------------------------------------------------------------------
extern "C" void kernel_launch(void* const* d_in, const int* in_sizes, int n_in,
                              void* d_out, int out_size) {
    const float* X = (const float*)d_in[0];
    const float* Y = (const float*)d_in[1];
    float* out = (float*)d_out;

    float z = 0.5f * (float)D_DIM * logf(2.0f * 3.14159265358979323846f)
            + logf((float)M_TRAIN);

    static int nsm = 0;
    if (!nsm) {
        cudaDeviceGetAttribute(&nsm, cudaDevAttrMultiProcessorCount, 0);
        if (nsm <= 0) nsm = 148;
        if (nsm > MAXCTAS) nsm = MAXCTAS;
        cudaFuncSetAttribute(kde_mma_kernel,
                             cudaFuncAttributeMaxDynamicSharedMemorySize, SMEM_TOTAL);
    }

    int warps = N_TEST + M_TRAIN;
    convert_kernel<<<(warps * 32 + 255) / 256, 256>>>(X, Y);
    kde_mma_kernel<<<nsm, THREADS, SMEM_TOTAL>>>();
    combine_kernel<<<(N_TEST + 255) / 256, 256>>>(out, z, nsm);
}

// round 15
// speedup vs baseline: 1.0084x; 1.0084x over previous
#include <cuda_runtime.h>
#include <cuda_fp16.h>
#include <math.h>
#include <stdint.h>

#define N_TEST  8192
#define M_TRAIN 16384
#define D_DIM   512
#define BM      128
#define BN      128
#define BK      64
#define THREADS 256
#define NCT     ((N_TEST / BM) * (M_TRAIN / BN))   // 8192 col-tiles
#define KSTEPS  (D_DIM / BK)                       // 8
#define MAXCTAS 512

#define AST 520                              // A smem row stride (u16)
#define BST 72                               // B smem row stride (u16), 144B = 9*16

#define SMEM_A        0
#define SMEM_A_BYTES  (BM * AST * 2)         // 133120
#define SMEM_B        SMEM_A_BYTES
#define B_STAGE_BYTES (BN * BST * 2)         // 18432
#define SMEM_YS       (SMEM_B + 4 * B_STAGE_BYTES)   // 206848
#define SMEM_RED      (SMEM_YS + 512)
#define SMEM_TOTAL    (SMEM_RED + 2048)              // 209408

// ---------------- device scratch ----------------
__device__ __half g_Xh[N_TEST * D_DIM];
__device__ __half g_Yh[M_TRAIN * D_DIM];
__device__ float g_x2s[N_TEST];      // -0.5*log2(e)*||x||^2
__device__ float g_y2s[M_TRAIN];     // -0.5*log2(e)*||y||^2
__device__ float g_pm[2 * MAXCTAS * BM];     // per (CTA, segment) partials
__device__ float g_ps[2 * MAXCTAS * BM];

// ---------------- helpers ----------------
__device__ __forceinline__ uint32_t smem_u32(const void* p) {
    uint32_t a;
    asm("{ .reg .u64 t; cvta.to.shared.u64 t, %1; cvt.u32.u64 %0, t; }" : "=r"(a) : "l"(p));
    return a;
}
__device__ __forceinline__ float ex2f(float x) {
    float y; asm("ex2.approx.ftz.f32 %0, %1;" : "=f"(y) : "f"(x)); return y;
}
__device__ __forceinline__ void cp16(uint32_t s, const void* g) {
    asm volatile("cp.async.cg.shared.global [%0], [%1], 16;" :: "r"(s), "l"(g));
}
#define CP_COMMIT() asm volatile("cp.async.commit_group;" ::: "memory")
#define CP_WAIT2()  asm volatile("cp.async.wait_group 2;" ::: "memory")

#define LDSM4(r, addr) \
    asm volatile("ldmatrix.sync.aligned.m8n8.x4.shared.b16 {%0,%1,%2,%3}, [%4];" \
        : "=r"((r)[0]), "=r"((r)[1]), "=r"((r)[2]), "=r"((r)[3]) : "r"(addr))
#define LDSM2(r, addr) \
    asm volatile("ldmatrix.sync.aligned.m8n8.x2.shared.b16 {%0,%1}, [%2];" \
        : "=r"((r)[0]), "=r"((r)[1]) : "r"(addr))

// fp16 inputs, fp16 accumulate (2 regs C/D)
#define MMA16816H(c, a, b) \
    asm volatile("mma.sync.aligned.m16n8k16.row.col.f16.f16.f16.f16 " \
        "{%0,%1},{%2,%3,%4,%5},{%6,%7},{%0,%1};" \
        : "+r"((c)[0]), "+r"((c)[1]) \
        : "r"((a)[0]), "r"((a)[1]), "r"((a)[2]), "r"((a)[3]), \
          "r"((b)[0]), "r"((b)[1]))

// ---------------------------------------------------------------------------
// Convert fp32 -> fp16 + scaled squared norms. One warp per row.
// ---------------------------------------------------------------------------
__global__ void convert_kernel(const float* __restrict__ X,
                               const float* __restrict__ Y) {
    const float NHL2E = -0.5f * 1.4426950408889634f;
    int gw   = (blockIdx.x * blockDim.x + threadIdx.x) >> 5;
    int lane = threadIdx.x & 31;
    if (gw >= N_TEST + M_TRAIN) return;

    const float* src;
    __half* dst;
    if (gw < N_TEST) { src = X + (size_t)gw * D_DIM; dst = g_Xh + (size_t)gw * D_DIM; }
    else { src = Y + (size_t)(gw - N_TEST) * D_DIM; dst = g_Yh + (size_t)(gw - N_TEST) * D_DIM; }

    const float4* p = (const float4*)(src + lane * 16);
    __half tmp[16];
    float s = 0.f;
#pragma unroll
    for (int j = 0; j < 4; ++j) {
        float4 v = p[j];
        s += v.x * v.x + v.y * v.y + v.z * v.z + v.w * v.w;
        tmp[4 * j + 0] = __float2half_rn(v.x);
        tmp[4 * j + 1] = __float2half_rn(v.y);
        tmp[4 * j + 2] = __float2half_rn(v.z);
        tmp[4 * j + 3] = __float2half_rn(v.w);
    }
    uint4* dv = (uint4*)(dst + lane * 16);
    dv[0] = ((uint4*)tmp)[0];
    dv[1] = ((uint4*)tmp)[1];
#pragma unroll
    for (int o = 16; o; o >>= 1) s += __shfl_xor_sync(0xffffffffu, s, o);
    if (lane == 0) {
        if (gw < N_TEST) g_x2s[gw] = NHL2E * s;
        else             g_y2s[gw - N_TEST] = NHL2E * s;
    }
}

// ---------------------------------------------------------------------------
// B stage fill: local stage l covers train rows [colbase + (l/8)*BN, +BN),
// k chunk (l%8)*64 elems (128 bytes/row). 256 threads x 4 cp16 = 16 KB.
// ---------------------------------------------------------------------------
__device__ __forceinline__ void fill_stage(uint32_t sb, int colbase, int l, int tid) {
    int buf = l & 3;
    int t   = l >> 3;
    int ks  = l & 7;
    int row = tid >> 1;               // 0..127
    int h   = (tid & 1) * 4;          // first 16B-chunk of this thread's 64B
    const __half* gp =
        g_Yh + ((size_t)(colbase + t * BN + row)) * D_DIM + ks * BK + h * 8;
    uint32_t sa = sb + SMEM_B + buf * B_STAGE_BYTES + (uint32_t)(row * BST + h * 8) * 2;
#pragma unroll
    for (int q = 0; q < 4; ++q)
        cp16(sa + q * 16, gp + q * 8);
}

// ---------------------------------------------------------------------------
// Persistent fused kernel: each CTA owns a contiguous range of the 8192
// rt-major col-tiles (<= 2 row-tile segments). One partial write per segment.
// ---------------------------------------------------------------------------
__global__ __launch_bounds__(THREADS, 1)
void kde_mma_kernel() {
    extern __shared__ __align__(16) unsigned char smem[];
    const uint32_t sb = smem_u32(smem);

    const int tid  = threadIdx.x;
    const int lane = tid & 31;
    const int warp = tid >> 5;
    const int wm   = warp & 3;
    const int wn   = warp >> 2;

    const int g = gridDim.x;
    int       i    = (int)(((long long)blockIdx.x * NCT) / g);
    const int iend = (int)(((long long)(blockIdx.x + 1) * NCT) / g);

    const uint32_t aRowBase = sb + SMEM_A +
        (uint32_t)((wm * 32 + (lane & 15)) * AST + (lane >> 4) * 8) * 2;
    const uint32_t bLaneOff =
        (uint32_t)((wn * 64 + (lane & 7)) * BST + ((lane >> 3) & 1) * 8) * 2;

    float* ysf  = (float*)(smem + SMEM_YS);
    float* redm = (float*)(smem + SMEM_RED);
    float* reds = (float*)(smem + SMEM_RED + 1024);
    const float L2E = 1.4426950408889634f;

    int seg = 0;
    while (i < iend) {
        const int rt     = i >> 7;
        const int segEnd = min(iend, (rt + 1) << 7);
        const int ntiles = segEnd - i;
        const int col0   = (i - (rt << 7)) * BN;
        const int row0   = rt * BM;
        const int ustages = ntiles * KSTEPS;

        // ---- A fill for this segment's row-tile ----
        {
            const __half* gp = g_Xh + (size_t)row0 * D_DIM;
#pragma unroll
            for (int q = 0; q < 32; ++q) {
                int f = tid + q * THREADS;
                int r = f >> 6, c = f & 63;
                cp16(sb + SMEM_A + (uint32_t)(r * AST + c * 8) * 2,
                     gp + (size_t)r * D_DIM + c * 8);
            }
            CP_COMMIT();
        }
        float x2p[4];
#pragma unroll
        for (int rg = 0; rg < 4; ++rg)
            x2p[rg] = g_x2s[row0 + wm * 32 + (rg >> 1) * 16 + (rg & 1) * 8 + (lane >> 2)];

        fill_stage(sb, col0, 0, tid); CP_COMMIT();
        fill_stage(sb, col0, 1, tid); CP_COMMIT();
        fill_stage(sb, col0, 2, tid); CP_COMMIT();

        float mrun[4], srun[4];
#pragma unroll
        for (int rg = 0; rg < 4; ++rg) { mrun[rg] = -INFINITY; srun[rg] = 0.f; }

#pragma unroll 1
        for (int t = 0; t < ntiles; ++t) {
            if (tid < BN) ysf[tid] = g_y2s[col0 + t * BN + tid];

            uint32_t acc[2][8][2];
#pragma unroll
            for (int mt = 0; mt < 2; ++mt)
#pragma unroll
                for (int nt = 0; nt < 8; ++nt) { acc[mt][nt][0] = 0u; acc[mt][nt][1] = 0u; }

#pragma unroll 1
            for (int ks = 0; ks < KSTEPS; ++ks) {
                const int l   = t * KSTEPS + ks;
                const int buf = l & 3;

                CP_WAIT2();            // stage l (and A on l=0) landed
                __syncthreads();
                if (l + 3 < ustages) fill_stage(sb, col0, l + 3, tid);
                CP_COMMIT();           // empty commits at the tail keep invariant

                const uint32_t bBase = sb + SMEM_B + buf * B_STAGE_BYTES + bLaneOff;
                const uint32_t aCol  = (uint32_t)(ks * BK) * 2;
#pragma unroll
                for (int kk = 0; kk < 4; ++kk) {
                    uint32_t a[2][4];
                    uint32_t aaddr = aRowBase + aCol + kk * 32;
                    LDSM4(a[0], aaddr);
                    LDSM4(a[1], aaddr + 16 * AST * 2);
                    uint32_t b[8][2];
#pragma unroll
                    for (int nt = 0; nt < 8; ++nt)
                        LDSM2(b[nt], bBase + kk * 32 + nt * 8 * BST * 2);
#pragma unroll
                    for (int mt = 0; mt < 2; ++mt)
#pragma unroll
                        for (int nt = 0; nt < 8; ++nt)
                            MMA16816H(acc[mt][nt], a[mt], b[nt]);
                }
            }

            // ---- epilogue: unpack fp16 accums, online logsumexp (f-domain) ----
            float2 yv[8];
#pragma unroll
            for (int nt = 0; nt < 8; ++nt)
                yv[nt] = *(const float2*)&ysf[wn * 64 + nt * 8 + (lane & 3) * 2];

#pragma unroll
            for (int rg = 0; rg < 4; ++rg) {
                const int mt = rg >> 1, hf = rg & 1;
                float e[16];
                float vmax = mrun[rg];
#pragma unroll
                for (int nt = 0; nt < 8; ++nt) {
                    float2 d = __half22float2(*(const __half2*)&acc[mt][nt][hf]);
                    float e0 = fmaf(d.x, L2E, yv[nt].x);
                    float e1 = fmaf(d.y, L2E, yv[nt].y);
                    e[nt * 2 + 0] = e0;
                    e[nt * 2 + 1] = e1;
                    vmax = fmaxf(vmax, fmaxf(e0, e1));
                }
                if (vmax > mrun[rg]) { srun[rg] *= ex2f(mrun[rg] - vmax); mrun[rg] = vmax; }
                float s0 = 0.f, s1 = 0.f;
#pragma unroll
                for (int j = 0; j < 16; j += 2) {
                    s0 += ex2f(e[j]     - mrun[rg]);
                    s1 += ex2f(e[j + 1] - mrun[rg]);
                }
                srun[rg] += s0 + s1;
            }
            __syncthreads();   // epilogue done before ys/buf reuse
        }

        // ---- per-segment reduction: quad shfl, then the 2 n-warps via smem ----
#pragma unroll
        for (int rg = 0; rg < 4; ++rg) {
            float m = mrun[rg] + x2p[rg];   // fold row constant back in
            float s = srun[rg];
#pragma unroll
            for (int off = 1; off <= 2; off <<= 1) {
                float mo = __shfl_xor_sync(0xffffffffu, m, off);
                float so = __shfl_xor_sync(0xffffffffu, s, off);
                float mx = fmaxf(m, mo);
                s = s * ex2f(m - mx) + so * ex2f(mo - mx);
                m = mx;
            }
            if ((lane & 3) == 0) {
                int r = wm * 32 + (rg >> 1) * 16 + (rg & 1) * 8 + (lane >> 2);
                redm[r * 2 + wn] = m;
                reds[r * 2 + wn] = s;
            }
        }
        __syncthreads();
        if (tid < BM) {
            float m0 = redm[tid * 2], m1 = redm[tid * 2 + 1];
            float s0 = reds[tid * 2], s1 = reds[tid * 2 + 1];
            float mx = fmaxf(m0, m1);
            float st = s0 * ex2f(m0 - mx) + s1 * ex2f(m1 - mx);
            int slot = blockIdx.x * 2 + seg;
            g_pm[slot * BM + tid] = mx;
            g_ps[slot * BM + tid] = st;
        }
        __syncthreads();   // red free before next segment

        seg++;
        i = segEnd;
    }
}

// ---------------------------------------------------------------------------
// Combine: for each output row, gather the (CTA, segment) slots whose
// col-tile range intersects this row-tile, and logsumexp-combine them.
// ---------------------------------------------------------------------------
__global__ void combine_kernel(float* __restrict__ out, float z, int g) {
    int r = blockIdx.x * blockDim.x + threadIdx.x;
    if (r >= N_TEST) return;
    int rt = r >> 7, rl = r & 127;

    int kmin = (int)(((long long)rt * 128 * g) / NCT) - 1;
    if (kmin < 0) kmin = 0;
    int kmax = (int)(((long long)(rt + 1) * 128 * g) / NCT) + 1;
    if (kmax > g - 1) kmax = g - 1;

    float m = -INFINITY, s = 0.f;
    for (int k = kmin; k <= kmax; ++k) {
        long long a0 = ((long long)k * NCT) / g;
        long long a1 = ((long long)(k + 1) * NCT) / g;
        int rt0 = (int)(a0 >> 7);
        int rtl = (int)((a1 - 1) >> 7);
        if (rt < rt0 || rt > rtl) continue;
        int slot = k * 2 + (rt - rt0);
        float mk = g_pm[slot * BM + rl];
        float sk = g_ps[slot * BM + rl];
        float mx = fmaxf(m, mk);
        s = s * ex2f(m - mx) + sk * ex2f(mk - mx);
        m = mx;
    }
    out[r] = m * 0.6931471805599453f + logf(s) - z;
}

// ---------------------------------------------------------------------------
extern "C" void kernel_launch(void* const* d_in, const int* in_sizes, int n_in,
                              void* d_out, int out_size) {
    const float* X = (const float*)d_in[0];
    const float* Y = (const float*)d_in[1];
    float* out = (float*)d_out;

    float z = 0.5f * (float)D_DIM * logf(2.0f * 3.14159265358979323846f)
            + logf((float)M_TRAIN);

    static int nsm = 0;
    if (!nsm) {
        cudaDeviceGetAttribute(&nsm, cudaDevAttrMultiProcessorCount, 0);
        if (nsm <= 0) nsm = 148;
        if (nsm > MAXCTAS) nsm = MAXCTAS;
        cudaFuncSetAttribute(kde_mma_kernel,
                             cudaFuncAttributeMaxDynamicSharedMemorySize, SMEM_TOTAL);
    }

    int warps = N_TEST + M_TRAIN;
    convert_kernel<<<(warps * 32 + 255) / 256, 256>>>(X, Y);
    kde_mma_kernel<<<nsm, THREADS, SMEM_TOTAL>>>();
    combine_kernel<<<(N_TEST + 255) / 256, 256>>>(out, z, nsm);
}

// round 16
// speedup vs baseline: 1.0100x; 1.0015x over previous
#include <cuda_runtime.h>
#include <cuda_fp16.h>
#include <math.h>
#include <stdint.h>

#define N_TEST  8192
#define M_TRAIN 16384
#define D_DIM   512
#define BM      128
#define BN      128
#define BK      64
#define THREADS 256
#define NCT     ((N_TEST / BM) * (M_TRAIN / BN))   // 8192 col-tiles
#define KSTEPS  (D_DIM / BK)                       // 8
#define MAXCTAS 512

#define AST 520                              // A smem row stride (u16)
#define BST 72                               // B smem row stride (u16), 144B = 9*16

#define SMEM_A        0
#define SMEM_A_BYTES  (BM * AST * 2)         // 133120
#define SMEM_B        SMEM_A_BYTES
#define B_STAGE_BYTES (BN * BST * 2)         // 18432
#define SMEM_YS       (SMEM_B + 4 * B_STAGE_BYTES)   // 206848
#define SMEM_RED      (SMEM_YS + 512)
#define SMEM_TOTAL    (SMEM_RED + 2048)              // 209408

// ---------------- device scratch ----------------
__device__ __half g_Xh[N_TEST * D_DIM];
__device__ __half g_Yh[M_TRAIN * D_DIM];
__device__ float g_x2s[N_TEST];      // -0.5*log2(e)*||x||^2
__device__ float g_y2s[M_TRAIN];     // -0.5*log2(e)*||y||^2
__device__ float g_pm[2 * MAXCTAS * BM];     // per (CTA, segment) partials
__device__ float g_ps[2 * MAXCTAS * BM];

// ---------------- helpers ----------------
__device__ __forceinline__ uint32_t smem_u32(const void* p) {
    uint32_t a;
    asm("{ .reg .u64 t; cvta.to.shared.u64 t, %1; cvt.u32.u64 %0, t; }" : "=r"(a) : "l"(p));
    return a;
}
__device__ __forceinline__ float ex2f(float x) {
    float y; asm("ex2.approx.ftz.f32 %0, %1;" : "=f"(y) : "f"(x)); return y;
}
__device__ __forceinline__ void cp16(uint32_t s, const void* g) {
    asm volatile("cp.async.cg.shared.global [%0], [%1], 16;" :: "r"(s), "l"(g));
}
#define CP_COMMIT() asm volatile("cp.async.commit_group;" ::: "memory")
#define CP_WAIT2()  asm volatile("cp.async.wait_group 2;" ::: "memory")

#define LDSM4(r, addr) \
    asm volatile("ldmatrix.sync.aligned.m8n8.x4.shared.b16 {%0,%1,%2,%3}, [%4];" \
        : "=r"((r)[0]), "=r"((r)[1]), "=r"((r)[2]), "=r"((r)[3]) : "r"(addr))
#define LDSM2(r, addr) \
    asm volatile("ldmatrix.sync.aligned.m8n8.x2.shared.b16 {%0,%1}, [%2];" \
        : "=r"((r)[0]), "=r"((r)[1]) : "r"(addr))

// fp16 inputs, fp16 accumulate (2 regs C/D)
#define MMA16816H(c, a, b) \
    asm volatile("mma.sync.aligned.m16n8k16.row.col.f16.f16.f16.f16 " \
        "{%0,%1},{%2,%3,%4,%5},{%6,%7},{%0,%1};" \
        : "+r"((c)[0]), "+r"((c)[1]) \
        : "r"((a)[0]), "r"((a)[1]), "r"((a)[2]), "r"((a)[3]), \
          "r"((b)[0]), "r"((b)[1]))

// ---------------------------------------------------------------------------
// Convert fp32 -> fp16 + scaled squared norms. One warp per row.
// ---------------------------------------------------------------------------
__global__ void convert_kernel(const float* __restrict__ X,
                               const float* __restrict__ Y) {
    const float NHL2E = -0.5f * 1.4426950408889634f;
    int gw   = (blockIdx.x * blockDim.x + threadIdx.x) >> 5;
    int lane = threadIdx.x & 31;
    if (gw >= N_TEST + M_TRAIN) return;

    const float* src;
    __half* dst;
    if (gw < N_TEST) { src = X + (size_t)gw * D_DIM; dst = g_Xh + (size_t)gw * D_DIM; }
    else { src = Y + (size_t)(gw - N_TEST) * D_DIM; dst = g_Yh + (size_t)(gw - N_TEST) * D_DIM; }

    const float4* p = (const float4*)(src + lane * 16);
    __half tmp[16];
    float s = 0.f;
#pragma unroll
    for (int j = 0; j < 4; ++j) {
        float4 v = p[j];
        s += v.x * v.x + v.y * v.y + v.z * v.z + v.w * v.w;
        tmp[4 * j + 0] = __float2half_rn(v.x);
        tmp[4 * j + 1] = __float2half_rn(v.y);
        tmp[4 * j + 2] = __float2half_rn(v.z);
        tmp[4 * j + 3] = __float2half_rn(v.w);
    }
    uint4* dv = (uint4*)(dst + lane * 16);
    dv[0] = ((uint4*)tmp)[0];
    dv[1] = ((uint4*)tmp)[1];
#pragma unroll
    for (int o = 16; o; o >>= 1) s += __shfl_xor_sync(0xffffffffu, s, o);
    if (lane == 0) {
        if (gw < N_TEST) g_x2s[gw] = NHL2E * s;
        else             g_y2s[gw - N_TEST] = NHL2E * s;
    }
}

// ---------------------------------------------------------------------------
// B stage fill: local stage l covers train rows [colbase + (l/8)*BN, +BN),
// k chunk (l%8)*64 elems (128 bytes/row). 256 threads x 4 cp16 = 16 KB.
// ---------------------------------------------------------------------------
__device__ __forceinline__ void fill_stage(uint32_t sb, int colbase, int l, int tid) {
    int buf = l & 3;
    int t   = l >> 3;
    int ks  = l & 7;
    int row = tid >> 1;               // 0..127
    int h   = (tid & 1) * 4;          // first 16B-chunk of this thread's 64B
    const __half* gp =
        g_Yh + ((size_t)(colbase + t * BN + row)) * D_DIM + ks * BK + h * 8;
    uint32_t sa = sb + SMEM_B + buf * B_STAGE_BYTES + (uint32_t)(row * BST + h * 8) * 2;
#pragma unroll
    for (int q = 0; q < 4; ++q)
        cp16(sa + q * 16, gp + q * 8);
}

// ---------------------------------------------------------------------------
// Persistent fused kernel: each CTA owns a contiguous range of the 8192
// rt-major col-tiles (<= 2 row-tile segments). One partial write per segment.
// ---------------------------------------------------------------------------
__global__ __launch_bounds__(THREADS, 1)
void kde_mma_kernel() {
    extern __shared__ __align__(16) unsigned char smem[];
    const uint32_t sb = smem_u32(smem);

    const int tid  = threadIdx.x;
    const int lane = tid & 31;
    const int warp = tid >> 5;
    const int wm   = warp & 3;
    const int wn   = warp >> 2;

    const int g = gridDim.x;
    int       i    = (int)(((long long)blockIdx.x * NCT) / g);
    const int iend = (int)(((long long)(blockIdx.x + 1) * NCT) / g);

    const uint32_t aRowBase = sb + SMEM_A +
        (uint32_t)((wm * 32 + (lane & 15)) * AST + (lane >> 4) * 8) * 2;
    const uint32_t bLaneOff =
        (uint32_t)((wn * 64 + (lane & 7)) * BST + ((lane >> 3) & 1) * 8) * 2;

    float* ysf  = (float*)(smem + SMEM_YS);
    float* redm = (float*)(smem + SMEM_RED);
    float* reds = (float*)(smem + SMEM_RED + 1024);
    const float L2E = 1.4426950408889634f;

    int seg = 0;
    while (i < iend) {
        const int rt     = i >> 7;
        const int segEnd = min(iend, (rt + 1) << 7);
        const int ntiles = segEnd - i;
        const int col0   = (i - (rt << 7)) * BN;
        const int row0   = rt * BM;
        const int ustages = ntiles * KSTEPS;

        // ---- A fill for this segment's row-tile ----
        {
            const __half* gp = g_Xh + (size_t)row0 * D_DIM;
#pragma unroll
            for (int q = 0; q < 32; ++q) {
                int f = tid + q * THREADS;
                int r = f >> 6, c = f & 63;
                cp16(sb + SMEM_A + (uint32_t)(r * AST + c * 8) * 2,
                     gp + (size_t)r * D_DIM + c * 8);
            }
            CP_COMMIT();
        }
        float x2p[4];
#pragma unroll
        for (int rg = 0; rg < 4; ++rg)
            x2p[rg] = g_x2s[row0 + wm * 32 + (rg >> 1) * 16 + (rg & 1) * 8 + (lane >> 2)];

        fill_stage(sb, col0, 0, tid); CP_COMMIT();
        fill_stage(sb, col0, 1, tid); CP_COMMIT();
        fill_stage(sb, col0, 2, tid); CP_COMMIT();

        float mrun[4], srun[4];
#pragma unroll
        for (int rg = 0; rg < 4; ++rg) { mrun[rg] = -INFINITY; srun[rg] = 0.f; }

#pragma unroll 1
        for (int t = 0; t < ntiles; ++t) {
            if (tid < BN) ysf[tid] = g_y2s[col0 + t * BN + tid];

            uint32_t acc[2][8][2];
#pragma unroll
            for (int mt = 0; mt < 2; ++mt)
#pragma unroll
                for (int nt = 0; nt < 8; ++nt) { acc[mt][nt][0] = 0u; acc[mt][nt][1] = 0u; }

#pragma unroll 1
            for (int ks = 0; ks < KSTEPS; ++ks) {
                const int l   = t * KSTEPS + ks;
                const int buf = l & 3;

                CP_WAIT2();            // stage l (and A on l=0) landed
                __syncthreads();
                if (l + 3 < ustages) fill_stage(sb, col0, l + 3, tid);
                CP_COMMIT();           // empty commits at the tail keep invariant

                const uint32_t bBase = sb + SMEM_B + buf * B_STAGE_BYTES + bLaneOff;
                const uint32_t aCol  = (uint32_t)(ks * BK) * 2;
#pragma unroll
                for (int kk = 0; kk < 4; ++kk) {
                    uint32_t a[2][4];
                    uint32_t aaddr = aRowBase + aCol + kk * 32;
                    LDSM4(a[0], aaddr);
                    LDSM4(a[1], aaddr + 16 * AST * 2);
                    uint32_t b[8][2];
#pragma unroll
                    for (int nt = 0; nt < 8; ++nt)
                        LDSM2(b[nt], bBase + kk * 32 + nt * 8 * BST * 2);
#pragma unroll
                    for (int mt = 0; mt < 2; ++mt)
#pragma unroll
                        for (int nt = 0; nt < 8; ++nt)
                            MMA16816H(acc[mt][nt], a[mt], b[nt]);
                }
            }

            // ---- epilogue: unpack fp16 accums, online logsumexp (f-domain) ----
            float2 yv[8];
#pragma unroll
            for (int nt = 0; nt < 8; ++nt)
                yv[nt] = *(const float2*)&ysf[wn * 64 + nt * 8 + (lane & 3) * 2];

#pragma unroll
            for (int rg = 0; rg < 4; ++rg) {
                const int mt = rg >> 1, hf = rg & 1;
                float e[16];
                float vmax = mrun[rg];
#pragma unroll
                for (int nt = 0; nt < 8; ++nt) {
                    float2 d = __half22float2(*(const __half2*)&acc[mt][nt][hf]);
                    float e0 = fmaf(d.x, L2E, yv[nt].x);
                    float e1 = fmaf(d.y, L2E, yv[nt].y);
                    e[nt * 2 + 0] = e0;
                    e[nt * 2 + 1] = e1;
                    vmax = fmaxf(vmax, fmaxf(e0, e1));
                }
                if (vmax > mrun[rg]) { srun[rg] *= ex2f(mrun[rg] - vmax); mrun[rg] = vmax; }
                float s0 = 0.f, s1 = 0.f;
#pragma unroll
                for (int j = 0; j < 16; j += 2) {
                    s0 += ex2f(e[j]     - mrun[rg]);
                    s1 += ex2f(e[j + 1] - mrun[rg]);
                }
                srun[rg] += s0 + s1;
            }
            __syncthreads();   // epilogue done before ys/buf reuse
        }

        // ---- per-segment reduction: quad shfl, then the 2 n-warps via smem ----
#pragma unroll
        for (int rg = 0; rg < 4; ++rg) {
            float m = mrun[rg] + x2p[rg];   // fold row constant back in
            float s = srun[rg];
#pragma unroll
            for (int off = 1; off <= 2; off <<= 1) {
                float mo = __shfl_xor_sync(0xffffffffu, m, off);
                float so = __shfl_xor_sync(0xffffffffu, s, off);
                float mx = fmaxf(m, mo);
                s = s * ex2f(m - mx) + so * ex2f(mo - mx);
                m = mx;
            }
            if ((lane & 3) == 0) {
                int r = wm * 32 + (rg >> 1) * 16 + (rg & 1) * 8 + (lane >> 2);
                redm[r * 2 + wn] = m;
                reds[r * 2 + wn] = s;
            }
        }
        __syncthreads();
        if (tid < BM) {
            float m0 = redm[tid * 2], m1 = redm[tid * 2 + 1];
            float s0 = reds[tid * 2], s1 = reds[tid * 2 + 1];
            float mx = fmaxf(m0, m1);
            float st = s0 * ex2f(m0 - mx) + s1 * ex2f(m1 - mx);
            int slot = blockIdx.x * 2 + seg;
            g_pm[slot * BM + tid] = mx;
            g_ps[slot * BM + tid] = st;
        }
        __syncthreads();   // red free before next segment

        seg++;
        i = segEnd;
    }
}

// ---------------------------------------------------------------------------
// Combine: for each output row, gather the (CTA, segment) slots whose
// col-tile range intersects this row-tile, and logsumexp-combine them.
// ---------------------------------------------------------------------------
__global__ void combine_kernel(float* __restrict__ out, float z, int g) {
    int r = blockIdx.x * blockDim.x + threadIdx.x;
    if (r >= N_TEST) return;
    int rt = r >> 7, rl = r & 127;

    int kmin = (int)(((long long)rt * 128 * g) / NCT) - 1;
    if (kmin < 0) kmin = 0;
    int kmax = (int)(((long long)(rt + 1) * 128 * g) / NCT) + 1;
    if (kmax > g - 1) kmax = g - 1;

    float m = -INFINITY, s = 0.f;
    for (int k = kmin; k <= kmax; ++k) {
        long long a0 = ((long long)k * NCT) / g;
        long long a1 = ((long long)(k + 1) * NCT) / g;
        int rt0 = (int)(a0 >> 7);
        int rtl = (int)((a1 - 1) >> 7);
        if (rt < rt0 || rt > rtl) continue;
        int slot = k * 2 + (rt - rt0);
        float mk = g_pm[slot * BM + rl];
        float sk = g_ps[slot * BM + rl];
        float mx = fmaxf(m, mk);
        s = s * ex2f(m - mx) + sk * ex2f(mk - mx);
        m = mx;
    }
    out[r] = m * 0.6931471805599453f + logf(s) - z;
}

// ---------------------------------------------------------------------------
extern "C" void kernel_launch(void* const* d_in, const int* in_sizes, int n_in,
                              void* d_out, int out_size) {
    const float* X = (const float*)d_in[0];
    const float* Y = (const float*)d_in[1];
    float* out = (float*)d_out;

    float z = 0.5f * (float)D_DIM * logf(2.0f * 3.14159265358979323846f)
            + logf((float)M_TRAIN);

    static int nsm = 0;
    if (!nsm) {
        cudaDeviceGetAttribute(&nsm, cudaDevAttrMultiProcessorCount, 0);
        if (nsm <= 0) nsm = 148;
        if (nsm > MAXCTAS) nsm = MAXCTAS;
        cudaFuncSetAttribute(kde_mma_kernel,
                             cudaFuncAttributeMaxDynamicSharedMemorySize, SMEM_TOTAL);
    }

    int warps = N_TEST + M_TRAIN;
    convert_kernel<<<(warps * 32 + 255) / 256, 256>>>(X, Y);
    kde_mma_kernel<<<nsm, THREADS, SMEM_TOTAL>>>();
    combine_kernel<<<(N_TEST + 255) / 256, 256>>>(out, z, nsm);
}